// round 14
// baseline (speedup 1.0000x reference)
#include <cuda_runtime.h>
#include <cstdint>

#define CB 2
#define CS 2048
#define CD 1024
#define CH 16
#define CHD 64
#define CBH (CB*CH)
#define CM (CB*CS)
#define OUT_ELEMS (CB*CS*CD)
#define ATTN_ELEMS ((size_t)CBH*CS*CS)
#define NKT (CS/128)

__device__ float g_q[CBH*CS*CHD];
__device__ float g_k[CBH*CS*CHD];
__device__ float g_v[CBH*CS*CHD];
__device__ float g_ctx[CBH*CS*CHD];
__device__ float g_attn_fb[(size_t)CBH*CS*CS];
__device__ float g_stat_max[(size_t)CBH*CS*NKT];
__device__ float g_stat_sum[(size_t)CBH*CS*NKT];
__device__ float g_row_m[CBH*CS];
__device__ float g_row_inv[CBH*CS];
__device__ int   g_mask_mode;

#define NEG_INF __int_as_float(0xff800000)

#define PROJ_SMEM (3*(128*36 + 32*132)*4)              // 105984
#define QK_SMEM   (3*2*128*20*4)                       // 61440
#define PV_SMEM   ((4*(128*20 + 16*72) + 4*128*20)*4)  // 100352

__global__ void detect_mask_kernel(const uint32_t* __restrict__ mask) {
    uint32_t w = mask[0];
    int mode = 0;
    if (w == 0x01010101u)      mode = 0;
    else if (w == 1u)          mode = 1;
    else if (w == 0x3F800000u) mode = 2;
    g_mask_mode = mode;
}

__device__ __forceinline__ uint32_t f2tf(float f) {
    uint32_t r;
    asm("cvt.rna.tf32.f32 %0, %1;" : "=r"(r) : "f"(f));
    return r;
}
__device__ __forceinline__ float f2tff(float f) { return __uint_as_float(f2tf(f)); }

__device__ __forceinline__ void mma8(float* c, const uint32_t* a, const uint32_t* b) {
    asm volatile(
        "mma.sync.aligned.m16n8k8.row.col.f32.tf32.tf32.f32 "
        "{%0,%1,%2,%3}, {%4,%5,%6,%7}, {%8,%9}, {%0,%1,%2,%3};"
        : "+f"(c[0]), "+f"(c[1]), "+f"(c[2]), "+f"(c[3])
        : "r"(a[0]), "r"(a[1]), "r"(a[2]), "r"(a[3]), "r"(b[0]), "r"(b[1]));
}

__device__ __forceinline__ void cpa16(const void* smem, const void* gmem) {
    uint32_t s = (uint32_t)__cvta_generic_to_shared(smem);
    asm volatile("cp.async.cg.shared.global [%0], [%1], 16;" :: "r"(s), "l"(gmem));
}
#define CP_COMMIT() asm volatile("cp.async.commit_group;")
#define CP_WAIT(n)  asm volatile("cp.async.wait_group %0;" :: "n"(n))

// ===========================================================================
// proj: BK=32, 3-stage. A smem [128][36], B smem [32][132]. Consumer cvt.
// ===========================================================================
__global__ void __launch_bounds__(256,2) proj_mma(
    const float* __restrict__ A, const float* __restrict__ W,
    const float* __restrict__ bias, float* __restrict__ dst)
{
    extern __shared__ float smem[];
    float (*sA)[128][36] = (float(*)[128][36])smem;
    float (*sB)[32][132] = (float(*)[32][132])(smem + 3*128*36);
    const int tid = threadIdx.x, warp = tid >> 5, lane = tid & 31;
    const int g = lane >> 2, tg = lane & 3;
    const int m0 = blockIdx.y * 128, n0 = blockIdx.x * 128;
    const int wm = (warp & 1) * 64, wn = (warp >> 1) * 32;

    const int arow = tid >> 1, ac = (tid & 1) * 16;
    const int brow = tid >> 3, bc = (tid & 7) * 16;

    auto loadAB = [&](int st, int k0) {
        const float* Ap = A + (size_t)(m0 + arow) * CD + k0 + ac;
        const float* Bp = W + (size_t)(k0 + brow) * CD + n0 + bc;
        #pragma unroll
        for (int q = 0; q < 4; ++q) {
            cpa16(&sA[st][arow][ac + 4*q], Ap + 4*q);
            cpa16(&sB[st][brow][bc + 4*q], Bp + 4*q);
        }
        CP_COMMIT();
    };

    loadAB(0, 0);
    loadAB(1, 32);

    float acc[4][4][4] = {};
    int stage = 0;
    for (int c = 0; c < 32; ++c) {
        CP_WAIT(1);
        __syncthreads();
        int pf = c + 2;
        if (pf < 32) {
            int st = stage + 2; if (st >= 3) st -= 3;
            loadAB(st, pf * 32);
        } else CP_COMMIT();
        #pragma unroll
        for (int ks = 0; ks < 4; ++ks) {
            const int kk = ks*8 + tg;
            uint32_t au[4][4], bu[4][2];
            #pragma unroll
            for (int i = 0; i < 4; ++i) {
                int m = wm + i*16 + g;
                au[i][0] = f2tf(sA[stage][m][kk]);
                au[i][1] = f2tf(sA[stage][m+8][kk]);
                au[i][2] = f2tf(sA[stage][m][kk+4]);
                au[i][3] = f2tf(sA[stage][m+8][kk+4]);
            }
            #pragma unroll
            for (int j = 0; j < 4; ++j) {
                int n = wn + j*8 + g;
                bu[j][0] = f2tf(sB[stage][kk][n]);
                bu[j][1] = f2tf(sB[stage][kk+4][n]);
            }
            #pragma unroll
            for (int i = 0; i < 4; ++i)
                #pragma unroll
                for (int j = 0; j < 4; ++j)
                    mma8(acc[i][j], au[i], bu[j]);
        }
        if (++stage >= 3) stage = 0;
    }

    #pragma unroll
    for (int i = 0; i < 4; ++i) {
        int r0 = m0 + wm + i*16 + g;
        int r1 = r0 + 8;
        int b0i = r0 >> 11, s0 = r0 & (CS-1);
        int b1i = r1 >> 11, s1 = r1 & (CS-1);
        #pragma unroll
        for (int j = 0; j < 4; ++j) {
            int col = n0 + wn + j*8 + 2*tg;
            int h = col >> 6, hd = col & 63;
            float2 bb = *(const float2*)(bias + col);
            float2 o0 = { f2tff(acc[i][j][0] + bb.x), f2tff(acc[i][j][1] + bb.y) };
            float2 o1 = { f2tff(acc[i][j][2] + bb.x), f2tff(acc[i][j][3] + bb.y) };
            *(float2*)&dst[((size_t)(b0i*CH + h)*CS + s0)*CHD + hd] = o0;
            *(float2*)&dst[((size_t)(b1i*CH + h)*CS + s1)*CHD + hd] = o1;
        }
    }
}

// ===========================================================================
// qk (unchanged from R13): raw scores + softmax tile stats.
// ===========================================================================
__global__ void __launch_bounds__(256,2) qk_mma(
    const void* __restrict__ maskp, float* __restrict__ scores)
{
    extern __shared__ float smem[];
    float (*sQ)[128][20] = (float(*)[128][20])smem;
    float (*sK)[128][20] = (float(*)[128][20])(smem + 3*128*20);
    const int tid = threadIdx.x, warp = tid >> 5, lane = tid & 31;
    const int g = lane >> 2, tg = lane & 3;
    const int bh = blockIdx.z;
    const int q0 = blockIdx.y * 128, k0t = blockIdx.x * 128;
    const int wm = (warp & 1) * 64, wn = (warp >> 1) * 32;
    const float* Qb = g_q + (size_t)bh * CS * CHD;
    const float* Kb = g_k + (size_t)bh * CS * CHD;

    const int arow = tid >> 2, aq = (tid & 3) * 4;

    auto loadQK = [&](int st, int d0) {
        cpa16(&sQ[st][arow][aq],      Qb + (size_t)(q0 + arow) * CHD + d0 + aq);
        cpa16(&sQ[st][64 + arow][aq], Qb + (size_t)(q0 + 64 + arow) * CHD + d0 + aq);
        cpa16(&sK[st][arow][aq],      Kb + (size_t)(k0t + arow) * CHD + d0 + aq);
        cpa16(&sK[st][64 + arow][aq], Kb + (size_t)(k0t + 64 + arow) * CHD + d0 + aq);
        CP_COMMIT();
    };

    loadQK(0, 0);
    loadQK(1, 16);

    float acc[4][4][4] = {};
    int stage = 0;
    for (int c = 0; c < 4; ++c) {
        CP_WAIT(1);
        __syncthreads();
        int pf = c + 2;
        if (pf < 4) {
            int st = stage + 2; if (st >= 3) st -= 3;
            loadQK(st, pf * 16);
        } else CP_COMMIT();
        #pragma unroll
        for (int ks = 0; ks < 2; ++ks) {
            const int kk = ks*8 + tg;
            uint32_t au[4][4], bu[4][2];
            #pragma unroll
            for (int i = 0; i < 4; ++i) {
                int m = wm + i*16 + g;
                au[i][0] = __float_as_uint(sQ[stage][m][kk]);
                au[i][1] = __float_as_uint(sQ[stage][m+8][kk]);
                au[i][2] = __float_as_uint(sQ[stage][m][kk+4]);
                au[i][3] = __float_as_uint(sQ[stage][m+8][kk+4]);
            }
            #pragma unroll
            for (int j = 0; j < 4; ++j) {
                int n = wn + j*8 + g;
                bu[j][0] = __float_as_uint(sK[stage][n][kk]);
                bu[j][1] = __float_as_uint(sK[stage][n][kk+4]);
            }
            #pragma unroll
            for (int i = 0; i < 4; ++i)
                #pragma unroll
                for (int j = 0; j < 4; ++j)
                    mma8(acc[i][j], au[i], bu[j]);
        }
        if (++stage >= 3) stage = 0;
    }

    const int mode = g_mask_mode;
    float* srow = scores + (size_t)bh * CS * CS;
    #pragma unroll
    for (int i = 0; i < 4; ++i) {
        int r0 = q0 + wm + i*16 + g;
        int r1 = r0 + 8;
        #pragma unroll
        for (int j = 0; j < 4; ++j) {
            int col = k0t + wn + j*8 + 2*tg;
            size_t off0 = (size_t)r0 * CS + col;
            size_t off1 = (size_t)r1 * CS + col;
            bool k00, k01, k10, k11;
            if (mode == 0) {
                uchar2 a = *(const uchar2*)((const unsigned char*)maskp + off0);
                uchar2 b = *(const uchar2*)((const unsigned char*)maskp + off1);
                k00 = a.x; k01 = a.y; k10 = b.x; k11 = b.y;
            } else if (mode == 1) {
                int2 a = *(const int2*)((const int*)maskp + off0);
                int2 b = *(const int2*)((const int*)maskp + off1);
                k00 = a.x; k01 = a.y; k10 = b.x; k11 = b.y;
            } else {
                float2 a = *(const float2*)((const float*)maskp + off0);
                float2 b = *(const float2*)((const float*)maskp + off1);
                k00 = a.x != 0.f; k01 = a.y != 0.f; k10 = b.x != 0.f; k11 = b.y != 0.f;
            }
            acc[i][j][0] = k00 ? acc[i][j][0]*0.125f : NEG_INF;
            acc[i][j][1] = k01 ? acc[i][j][1]*0.125f : NEG_INF;
            acc[i][j][2] = k10 ? acc[i][j][2]*0.125f : NEG_INF;
            acc[i][j][3] = k11 ? acc[i][j][3]*0.125f : NEG_INF;
            *(float2*)(srow + off0) = *(float2*)&acc[i][j][0];
            *(float2*)(srow + off1) = *(float2*)&acc[i][j][2];
        }
    }

    float* sred = smem;
    float* ssum = smem + 512;
    const int wnIdx = warp >> 1;
    __syncthreads();

    float rmax[4][2];
    #pragma unroll
    for (int i = 0; i < 4; ++i)
        #pragma unroll
        for (int h = 0; h < 2; ++h) {
            float m = NEG_INF;
            #pragma unroll
            for (int j = 0; j < 4; ++j) {
                m = fmaxf(m, acc[i][j][2*h]);
                m = fmaxf(m, acc[i][j][2*h+1]);
            }
            m = fmaxf(m, __shfl_xor_sync(0xffffffffu, m, 1));
            m = fmaxf(m, __shfl_xor_sync(0xffffffffu, m, 2));
            rmax[i][h] = m;
        }
    if (tg == 0) {
        #pragma unroll
        for (int i = 0; i < 4; ++i)
            #pragma unroll
            for (int h = 0; h < 2; ++h)
                sred[wnIdx*128 + wm + i*16 + h*8 + g] = rmax[i][h];
    }
    __syncthreads();
    #pragma unroll
    for (int i = 0; i < 4; ++i)
        #pragma unroll
        for (int h = 0; h < 2; ++h) {
            int rl = wm + i*16 + h*8 + g;
            rmax[i][h] = fmaxf(fmaxf(sred[rl], sred[128+rl]),
                               fmaxf(sred[256+rl], sred[384+rl]));
        }
    float rsum[4][2];
    #pragma unroll
    for (int i = 0; i < 4; ++i)
        #pragma unroll
        for (int h = 0; h < 2; ++h) {
            float m = rmax[i][h];
            float s = 0.f;
            #pragma unroll
            for (int j = 0; j < 4; ++j) {
                float v0 = acc[i][j][2*h], v1 = acc[i][j][2*h+1];
                s += (v0 == NEG_INF) ? 0.f : __expf(v0 - m);
                s += (v1 == NEG_INF) ? 0.f : __expf(v1 - m);
            }
            s += __shfl_xor_sync(0xffffffffu, s, 1);
            s += __shfl_xor_sync(0xffffffffu, s, 2);
            rsum[i][h] = s;
        }
    if (tg == 0) {
        #pragma unroll
        for (int i = 0; i < 4; ++i)
            #pragma unroll
            for (int h = 0; h < 2; ++h)
                ssum[wnIdx*128 + wm + i*16 + h*8 + g] = rsum[i][h];
    }
    __syncthreads();
    if (wnIdx == 0 && tg == 0) {
        #pragma unroll
        for (int i = 0; i < 4; ++i)
            #pragma unroll
            for (int h = 0; h < 2; ++h) {
                int rl = wm + i*16 + h*8 + g;
                float s = ssum[rl] + ssum[128+rl] + ssum[256+rl] + ssum[384+rl];
                size_t sidx = ((size_t)bh*CS + q0 + rl)*NKT + blockIdx.x;
                g_stat_max[sidx] = rmax[i][h];
                g_stat_sum[sidx] = s;
            }
    }
}

// ===========================================================================
__global__ void __launch_bounds__(256) stat_reduce()
{
    int idx = blockIdx.x * 256 + threadIdx.x;
    const float* pm = g_stat_max + (size_t)idx * NKT;
    const float* ps = g_stat_sum + (size_t)idx * NKT;
    float M = NEG_INF;
    #pragma unroll
    for (int t = 0; t < NKT; ++t) M = fmaxf(M, pm[t]);
    float S = 0.f;
    #pragma unroll
    for (int t = 0; t < NKT; ++t) S += ps[t] * __expf(pm[t] - M);
    g_row_m[idx] = M;
    g_row_inv[idx] = 1.0f / S;
}

// ===========================================================================
// pv (unchanged from R13): exp-once writer phase + pure-LDS consumers.
// ===========================================================================
__global__ void __launch_bounds__(256,2) pv_mma(float* __restrict__ attn)
{
    extern __shared__ float smem[];
    float (*sP)[128][20]  = (float(*)[128][20])smem;
    float (*sV)[16][72]   = (float(*)[16][72])(smem + 4*128*20);
    float (*sPr)[128][20] = (float(*)[128][20])(smem + 4*128*20 + 4*16*72);
    const int tid = threadIdx.x, warp = tid >> 5, lane = tid & 31;
    const int g = lane >> 2, tg = lane & 3;
    const int bh = blockIdx.y, m0 = blockIdx.x * 128;
    const int wm = (warp & 3) * 32, wn = (warp >> 2) * 32;
    float* Ab = attn + (size_t)bh * CS * CS;
    const float* Vb = g_v + (size_t)bh * CS * CHD;

    const int arow = tid >> 2, aq = (tid & 3) * 4;
    const int vrow = tid >> 4, vq = (tid & 15) * 4;

    const float rm0 = g_row_m[bh*CS + m0 + arow];
    const float ri0 = g_row_inv[bh*CS + m0 + arow];
    const float rm1 = g_row_m[bh*CS + m0 + 64 + arow];
    const float ri1 = g_row_inv[bh*CS + m0 + 64 + arow];

    auto loadPV = [&](int st, int k0) {
        cpa16(&sP[st][arow][aq],      Ab + (size_t)(m0 + arow) * CS + k0 + aq);
        cpa16(&sP[st][64 + arow][aq], Ab + (size_t)(m0 + 64 + arow) * CS + k0 + aq);
        cpa16(&sV[st][vrow][vq],      Vb + (size_t)(k0 + vrow) * CHD + vq);
        CP_COMMIT();
    };

    loadPV(0, 0);
    loadPV(1, 16);
    loadPV(2, 32);

    float acc[2][4][4] = {};
    int stage = 0;
    for (int c = 0; c < 128; ++c) {
        CP_WAIT(2);
        __syncthreads();
        int pf = c + 3;
        if (pf < 128) loadPV((stage + 3) & 3, pf * 16);
        else CP_COMMIT();

        {
            const int k0 = c * 16;
            float4 v0 = *(float4*)&sP[stage][arow][aq];
            float4 v1 = *(float4*)&sP[stage][64 + arow][aq];
            v0.x = __expf(v0.x - rm0) * ri0;
            v0.y = __expf(v0.y - rm0) * ri0;
            v0.z = __expf(v0.z - rm0) * ri0;
            v0.w = __expf(v0.w - rm0) * ri0;
            v1.x = __expf(v1.x - rm1) * ri1;
            v1.y = __expf(v1.y - rm1) * ri1;
            v1.z = __expf(v1.z - rm1) * ri1;
            v1.w = __expf(v1.w - rm1) * ri1;
            *(float4*)&Ab[(size_t)(m0 + arow) * CS + k0 + aq]      = v0;
            *(float4*)&Ab[(size_t)(m0 + 64 + arow) * CS + k0 + aq] = v1;
            float4 r0 = { f2tff(v0.x), f2tff(v0.y), f2tff(v0.z), f2tff(v0.w) };
            float4 r1 = { f2tff(v1.x), f2tff(v1.y), f2tff(v1.z), f2tff(v1.w) };
            *(float4*)&sPr[stage][arow][aq]      = r0;
            *(float4*)&sPr[stage][64 + arow][aq] = r1;
        }
        __syncthreads();

        #pragma unroll
        for (int ks = 0; ks < 2; ++ks) {
            const int kk = ks*8 + tg;
            uint32_t au[2][4], bu[4][2];
            #pragma unroll
            for (int i = 0; i < 2; ++i) {
                int m = wm + i*16 + g;
                au[i][0] = __float_as_uint(sPr[stage][m][kk]);
                au[i][1] = __float_as_uint(sPr[stage][m+8][kk]);
                au[i][2] = __float_as_uint(sPr[stage][m][kk+4]);
                au[i][3] = __float_as_uint(sPr[stage][m+8][kk+4]);
            }
            #pragma unroll
            for (int j = 0; j < 4; ++j) {
                int n = wn + j*8 + g;
                bu[j][0] = __float_as_uint(sV[stage][kk][n]);
                bu[j][1] = __float_as_uint(sV[stage][kk+4][n]);
            }
            #pragma unroll
            for (int i = 0; i < 2; ++i)
                #pragma unroll
                for (int j = 0; j < 4; ++j)
                    mma8(acc[i][j], au[i], bu[j]);
        }
        stage = (stage + 1) & 3;
    }

    float* ctxb = g_ctx + (size_t)bh * CS * CHD;
    #pragma unroll
    for (int i = 0; i < 2; ++i) {
        int r0 = m0 + wm + i*16 + g;
        int r1 = r0 + 8;
        #pragma unroll
        for (int j = 0; j < 4; ++j) {
            int col = wn + j*8 + 2*tg;
            float2 o0 = { f2tff(acc[i][j][0]), f2tff(acc[i][j][1]) };
            float2 o1 = { f2tff(acc[i][j][2]), f2tff(acc[i][j][3]) };
            *(float2*)&ctxb[(size_t)r0 * CHD + col] = o0;
            *(float2*)&ctxb[(size_t)r1 * CHD + col] = o1;
        }
    }
}

// ===========================================================================
// outproj: BK=32, 3-stage, ctx gather + Wo consumer cvt.
// ===========================================================================
__global__ void __launch_bounds__(256,2) outproj_mma(
    const float* __restrict__ W, const float* __restrict__ bias, float* __restrict__ out)
{
    extern __shared__ float smem[];
    float (*sA)[128][36] = (float(*)[128][36])smem;
    float (*sB)[32][132] = (float(*)[32][132])(smem + 3*128*36);
    const int tid = threadIdx.x, warp = tid >> 5, lane = tid & 31;
    const int g = lane >> 2, tg = lane & 3;
    const int m0 = blockIdx.y * 128, n0 = blockIdx.x * 128;
    const int wm = (warp & 1) * 64, wn = (warp >> 1) * 32;

    const int arow = tid >> 1, ac = (tid & 1) * 16;
    const int brow = tid >> 3, bc = (tid & 7) * 16;

    const int mA = m0 + arow, bA = mA >> 11, sAr = mA & (CS-1);
    const float* ctxp = g_ctx + ((size_t)bA*CH*CS + sAr) * CHD;

    auto loadAB = [&](int st, int k0) {
        const float* Bp = W + (size_t)(k0 + brow) * CD + n0 + bc;
        #pragma unroll
        for (int q = 0; q < 4; ++q) {
            int k = k0 + ac + 4*q;
            cpa16(&sA[st][arow][ac + 4*q], ctxp + (size_t)(k >> 6) * CS * CHD + (k & 63));
            cpa16(&sB[st][brow][bc + 4*q], Bp + 4*q);
        }
        CP_COMMIT();
    };

    loadAB(0, 0);
    loadAB(1, 32);

    float acc[4][4][4] = {};
    int stage = 0;
    for (int c = 0; c < 32; ++c) {
        CP_WAIT(1);
        __syncthreads();
        int pf = c + 2;
        if (pf < 32) {
            int st = stage + 2; if (st >= 3) st -= 3;
            loadAB(st, pf * 32);
        } else CP_COMMIT();
        #pragma unroll
        for (int ks = 0; ks < 4; ++ks) {
            const int kk = ks*8 + tg;
            uint32_t au[4][4], bu[4][2];
            #pragma unroll
            for (int i = 0; i < 4; ++i) {
                int m = wm + i*16 + g;
                au[i][0] = __float_as_uint(sA[stage][m][kk]);
                au[i][1] = __float_as_uint(sA[stage][m+8][kk]);
                au[i][2] = __float_as_uint(sA[stage][m][kk+4]);
                au[i][3] = __float_as_uint(sA[stage][m+8][kk+4]);
            }
            #pragma unroll
            for (int j = 0; j < 4; ++j) {
                int n = wn + j*8 + g;
                bu[j][0] = f2tf(sB[stage][kk][n]);
                bu[j][1] = f2tf(sB[stage][kk+4][n]);
            }
            #pragma unroll
            for (int i = 0; i < 4; ++i)
                #pragma unroll
                for (int j = 0; j < 4; ++j)
                    mma8(acc[i][j], au[i], bu[j]);
        }
        if (++stage >= 3) stage = 0;
    }

    #pragma unroll
    for (int i = 0; i < 4; ++i) {
        int r0 = m0 + wm + i*16 + g;
        int r1 = r0 + 8;
        #pragma unroll
        for (int j = 0; j < 4; ++j) {
            int col = n0 + wn + j*8 + 2*tg;
            float2 bb = *(const float2*)(bias + col);
            float2 o0 = { acc[i][j][0] + bb.x, acc[i][j][1] + bb.y };
            float2 o1 = { acc[i][j][2] + bb.x, acc[i][j][3] + bb.y };
            *(float2*)&out[(size_t)r0 * CD + col] = o0;
            *(float2*)&out[(size_t)r1 * CD + col] = o1;
        }
    }
}

// ===========================================================================
extern "C" void kernel_launch(void* const* d_in, const int* in_sizes, int n_in,
                              void* d_out, int out_size) {
    const float* query = (const float*)d_in[0];
    const float* key_  = (const float*)d_in[1];
    const float* value = (const float*)d_in[2];
    const float* Wq = (const float*)d_in[3];
    const float* bq = (const float*)d_in[4];
    const float* Wk = (const float*)d_in[5];
    const float* bk = (const float*)d_in[6];
    const float* Wv = (const float*)d_in[7];
    const float* bv = (const float*)d_in[8];
    const float* Wo = (const float*)d_in[9];
    const float* bo = (const float*)d_in[10];
    const void*  mask = d_in[11];

    float* out = (float*)d_out;
    float *qp, *kp, *vp, *attn;
    cudaGetSymbolAddress((void**)&qp, g_q);
    cudaGetSymbolAddress((void**)&kp, g_k);
    cudaGetSymbolAddress((void**)&vp, g_v);
    if ((size_t)out_size >= (size_t)OUT_ELEMS + ATTN_ELEMS) {
        attn = out + OUT_ELEMS;
    } else {
        cudaGetSymbolAddress((void**)&attn, g_attn_fb);
    }

    cudaFuncSetAttribute(proj_mma,    cudaFuncAttributeMaxDynamicSharedMemorySize, PROJ_SMEM);
    cudaFuncSetAttribute(qk_mma,      cudaFuncAttributeMaxDynamicSharedMemorySize, QK_SMEM);
    cudaFuncSetAttribute(pv_mma,      cudaFuncAttributeMaxDynamicSharedMemorySize, PV_SMEM);
    cudaFuncSetAttribute(outproj_mma, cudaFuncAttributeMaxDynamicSharedMemorySize, PROJ_SMEM);

    detect_mask_kernel<<<1, 1>>>((const uint32_t*)mask);

    dim3 pg(CD/128, CM/128);
    proj_mma<<<pg, 256, PROJ_SMEM>>>(query, Wq, bq, qp);
    proj_mma<<<pg, 256, PROJ_SMEM>>>(key_,  Wk, bk, kp);
    proj_mma<<<pg, 256, PROJ_SMEM>>>(value, Wv, bv, vp);

    qk_mma<<<dim3(CS/128, CS/128, CBH), 256, QK_SMEM>>>(mask, attn);
    stat_reduce<<<CBH*CS/256, 256>>>();
    pv_mma<<<dim3(CS/128, CBH), 256, PV_SMEM>>>(attn);
    outproj_mma<<<dim3(CD/128, CM/128), 256, PROJ_SMEM>>>(Wo, bo, out);
}

// round 15
// speedup vs baseline: 1.0357x; 1.0357x over previous
#include <cuda_runtime.h>
#include <cstdint>

#define CB 2
#define CS 2048
#define CD 1024
#define CH 16
#define CHD 64
#define CBH (CB*CH)
#define CM (CB*CS)
#define OUT_ELEMS (CB*CS*CD)
#define ATTN_ELEMS ((size_t)CBH*CS*CS)
#define NKT (CS/128)

__device__ float g_q[CBH*CS*CHD];
__device__ float g_k[CBH*CS*CHD];
__device__ float g_v[CBH*CS*CHD];
__device__ float g_ctx[CBH*CS*CHD];
__device__ float g_attn_fb[(size_t)CBH*CS*CS];
__device__ int   g_mask_mode;

#define NEG_INF __int_as_float(0xff800000)

#define PROJ_SMEM (4*(128*20 + 16*132)*4)              // 74752
// fused attn smem (floats):
//  union region: pass1 = sQf 128*68 (8704) + sK 3*128*20 (7680) = 16384
//                pass2 = sP 4*128*20 (10240) + sV 4*16*72 (4608) + sPr 10240 = 25088
//  then sM(128) sS(128) sred(512) ssum(512)
#define FUSED_FLOATS (25088 + 128 + 128 + 512 + 512)
#define FUSED_SMEM   (FUSED_FLOATS*4)                   // 105472

__global__ void detect_mask_kernel(const uint32_t* __restrict__ mask) {
    uint32_t w = mask[0];
    int mode = 0;
    if (w == 0x01010101u)      mode = 0;
    else if (w == 1u)          mode = 1;
    else if (w == 0x3F800000u) mode = 2;
    g_mask_mode = mode;
}

__device__ __forceinline__ uint32_t f2tf(float f) {
    uint32_t r;
    asm("cvt.rna.tf32.f32 %0, %1;" : "=r"(r) : "f"(f));
    return r;
}
__device__ __forceinline__ float f2tff(float f) { return __uint_as_float(f2tf(f)); }

__device__ __forceinline__ void mma8(float* c, const uint32_t* a, const uint32_t* b) {
    asm volatile(
        "mma.sync.aligned.m16n8k8.row.col.f32.tf32.tf32.f32 "
        "{%0,%1,%2,%3}, {%4,%5,%6,%7}, {%8,%9}, {%0,%1,%2,%3};"
        : "+f"(c[0]), "+f"(c[1]), "+f"(c[2]), "+f"(c[3])
        : "r"(a[0]), "r"(a[1]), "r"(a[2]), "r"(a[3]), "r"(b[0]), "r"(b[1]));
}

__device__ __forceinline__ void cpa16(const void* smem, const void* gmem) {
    uint32_t s = (uint32_t)__cvta_generic_to_shared(smem);
    asm volatile("cp.async.cg.shared.global [%0], [%1], 16;" :: "r"(s), "l"(gmem));
}
#define CP_COMMIT() asm volatile("cp.async.commit_group;")
#define CP_WAIT(n)  asm volatile("cp.async.wait_group %0;" :: "n"(n))

// ===========================================================================
// proj (R13): 4-stage BK=16, consumer cvt, writes rounded dst -> [B,H,S,HD].
// ===========================================================================
__global__ void __launch_bounds__(256,2) proj_mma(
    const float* __restrict__ A, const float* __restrict__ W,
    const float* __restrict__ bias, float* __restrict__ dst)
{
    extern __shared__ float smem[];
    float (*sA)[128][20] = (float(*)[128][20])smem;
    float (*sB)[16][132] = (float(*)[16][132])(smem + 4*128*20);
    const int tid = threadIdx.x, warp = tid >> 5, lane = tid & 31;
    const int g = lane >> 2, tg = lane & 3;
    const int m0 = blockIdx.y * 128, n0 = blockIdx.x * 128;
    const int wm = (warp & 1) * 64, wn = (warp >> 1) * 32;

    const int arow = tid >> 2, aq = (tid & 3) * 4;
    const int brow = tid >> 5, bq = (tid & 31) * 4;

    auto loadAB = [&](int st, int k0) {
        cpa16(&sA[st][arow][aq],      A + (size_t)(m0 + arow) * CD + k0 + aq);
        cpa16(&sA[st][64 + arow][aq], A + (size_t)(m0 + 64 + arow) * CD + k0 + aq);
        cpa16(&sB[st][brow][bq],      W + (size_t)(k0 + brow) * CD + n0 + bq);
        cpa16(&sB[st][8 + brow][bq],  W + (size_t)(k0 + 8 + brow) * CD + n0 + bq);
        CP_COMMIT();
    };

    loadAB(0, 0);
    loadAB(1, 16);
    loadAB(2, 32);

    float acc[4][4][4] = {};
    int stage = 0;
    for (int c = 0; c < 64; ++c) {
        CP_WAIT(2);
        __syncthreads();
        int pf = c + 3;
        if (pf < 64) loadAB((stage + 3) & 3, pf * 16);
        else CP_COMMIT();
        #pragma unroll
        for (int ks = 0; ks < 2; ++ks) {
            const int kk = ks*8 + tg;
            uint32_t au[4][4], bu[4][2];
            #pragma unroll
            for (int i = 0; i < 4; ++i) {
                int m = wm + i*16 + g;
                au[i][0] = f2tf(sA[stage][m][kk]);
                au[i][1] = f2tf(sA[stage][m+8][kk]);
                au[i][2] = f2tf(sA[stage][m][kk+4]);
                au[i][3] = f2tf(sA[stage][m+8][kk+4]);
            }
            #pragma unroll
            for (int j = 0; j < 4; ++j) {
                int n = wn + j*8 + g;
                bu[j][0] = f2tf(sB[stage][kk][n]);
                bu[j][1] = f2tf(sB[stage][kk+4][n]);
            }
            #pragma unroll
            for (int i = 0; i < 4; ++i)
                #pragma unroll
                for (int j = 0; j < 4; ++j)
                    mma8(acc[i][j], au[i], bu[j]);
        }
        stage = (stage + 1) & 3;
    }

    #pragma unroll
    for (int i = 0; i < 4; ++i) {
        int r0 = m0 + wm + i*16 + g;
        int r1 = r0 + 8;
        int b0i = r0 >> 11, s0 = r0 & (CS-1);
        int b1i = r1 >> 11, s1 = r1 & (CS-1);
        #pragma unroll
        for (int j = 0; j < 4; ++j) {
            int col = n0 + wn + j*8 + 2*tg;
            int h = col >> 6, hd = col & 63;
            float2 bb = *(const float2*)(bias + col);
            float2 o0 = { f2tff(acc[i][j][0] + bb.x), f2tff(acc[i][j][1] + bb.y) };
            float2 o1 = { f2tff(acc[i][j][2] + bb.x), f2tff(acc[i][j][3] + bb.y) };
            *(float2*)&dst[((size_t)(b0i*CH + h)*CS + s0)*CHD + hd] = o0;
            *(float2*)&dst[((size_t)(b1i*CH + h)*CS + s1)*CHD + hd] = o1;
        }
    }
}

// ===========================================================================
// attn_fused: per (q-tile, bh) CTA.
// Pass 1: Q resident; K streamed (64 flattened 16-d chunks, 3-stage);
//         per k-tile: raw scores out + online (M,S) merge in smem.
// Pass 2: R13 pv body; row stats from smem; score readback L2-hot.
// ===========================================================================
__global__ void __launch_bounds__(256,2) attn_fused(
    const void* __restrict__ maskp, float* __restrict__ attn)
{
    extern __shared__ float smem[];
    // pass1 views
    float (*sQf)[68]     = (float(*)[68])smem;                    // [128][68]
    float (*sK)[128][20] = (float(*)[128][20])(smem + 8704);      // [3][128][20]
    // pass2 views (alias union region)
    float (*sP)[128][20]  = (float(*)[128][20])smem;              // [4]
    float (*sV)[16][72]   = (float(*)[16][72])(smem + 4*128*20);
    float (*sPr)[128][20] = (float(*)[128][20])(smem + 4*128*20 + 4*16*72);
    float* sM   = smem + 25088;
    float* sS   = smem + 25088 + 128;
    float* sred = smem + 25088 + 256;
    float* ssum = smem + 25088 + 256 + 512;

    const int tid = threadIdx.x, warp = tid >> 5, lane = tid & 31;
    const int g = lane >> 2, tg = lane & 3;
    const int qt = blockIdx.x, bh = blockIdx.y;
    const int q0 = qt * 128;
    const float* Qb = g_q + (size_t)bh * CS * CHD;
    const float* Kb = g_k + (size_t)bh * CS * CHD;
    const float* Vb = g_v + (size_t)bh * CS * CHD;
    float* Ab = attn + ((size_t)bh * CS + q0) * CS;   // rows q0..q0+127

    // ---- init running stats ----
    if (tid < 128) { sM[tid] = NEG_INF; sS[tid] = 0.f; }

    // ---- load Q tile resident: [128][64] -> sQf[128][68] ----
    {
        const int row = tid >> 1, c0 = (tid & 1) * 32;
        const float* qp = Qb + (size_t)(q0 + row) * CHD + c0;
        #pragma unroll
        for (int qq = 0; qq < 8; ++qq)
            cpa16(&sQf[row][c0 + 4*qq], qp + 4*qq);
        CP_COMMIT();
    }

    const int krow = tid >> 2, kq = (tid & 3) * 4;
    auto loadK = [&](int st, int chunk) {            // chunk = t*4 + d4
        const int k0t = (chunk >> 2) * 128, d0 = (chunk & 3) * 16;
        cpa16(&sK[st][krow][kq],      Kb + (size_t)(k0t + krow) * CHD + d0 + kq);
        cpa16(&sK[st][64 + krow][kq], Kb + (size_t)(k0t + 64 + krow) * CHD + d0 + kq);
        CP_COMMIT();
    };
    loadK(0, 0);
    loadK(1, 1);

    const int wm1 = (warp & 1) * 64, wn1 = (warp >> 1) * 32;
    const int mode = g_mask_mode;

    float acc[4][4][4] = {};
    int stage = 0;
    for (int q = 0; q < 64; ++q) {
        CP_WAIT(1);
        __syncthreads();
        int pf = q + 2;
        if (pf < 64) {
            int st = stage + 2; if (st >= 3) st -= 3;
            loadK(st, pf);
        } else CP_COMMIT();

        const int dbase = (q & 3) * 16;
        #pragma unroll
        for (int ks = 0; ks < 2; ++ks) {
            const int kk = ks*8 + tg;
            const int dd = dbase + kk;
            uint32_t au[4][4], bu[4][2];
            #pragma unroll
            for (int i = 0; i < 4; ++i) {
                int m = wm1 + i*16 + g;
                au[i][0] = __float_as_uint(sQf[m][dd]);
                au[i][1] = __float_as_uint(sQf[m+8][dd]);
                au[i][2] = __float_as_uint(sQf[m][dd+4]);
                au[i][3] = __float_as_uint(sQf[m+8][dd+4]);
            }
            #pragma unroll
            for (int j = 0; j < 4; ++j) {
                int n = wn1 + j*8 + g;
                bu[j][0] = __float_as_uint(sK[stage][n][kk]);
                bu[j][1] = __float_as_uint(sK[stage][n][kk+4]);
            }
            #pragma unroll
            for (int i = 0; i < 4; ++i)
                #pragma unroll
                for (int j = 0; j < 4; ++j)
                    mma8(acc[i][j], au[i], bu[j]);
        }

        if ((q & 3) == 3) {
            // ---- tile epilogue for k-tile t ----
            const int k0t = (q >> 2) * 128;
            #pragma unroll
            for (int i = 0; i < 4; ++i) {
                int lr0 = wm1 + i*16 + g;
                int r0 = q0 + lr0, r1 = r0 + 8;
                #pragma unroll
                for (int j = 0; j < 4; ++j) {
                    int col = k0t + wn1 + j*8 + 2*tg;
                    size_t off0 = (size_t)r0 * CS + col;
                    size_t off1 = (size_t)r1 * CS + col;
                    bool k00, k01, k10, k11;
                    if (mode == 0) {
                        uchar2 a = *(const uchar2*)((const unsigned char*)maskp + off0);
                        uchar2 b = *(const uchar2*)((const unsigned char*)maskp + off1);
                        k00 = a.x; k01 = a.y; k10 = b.x; k11 = b.y;
                    } else if (mode == 1) {
                        int2 a = *(const int2*)((const int*)maskp + off0);
                        int2 b = *(const int2*)((const int*)maskp + off1);
                        k00 = a.x; k01 = a.y; k10 = b.x; k11 = b.y;
                    } else {
                        float2 a = *(const float2*)((const float*)maskp + off0);
                        float2 b = *(const float2*)((const float*)maskp + off1);
                        k00 = a.x != 0.f; k01 = a.y != 0.f; k10 = b.x != 0.f; k11 = b.y != 0.f;
                    }
                    acc[i][j][0] = k00 ? acc[i][j][0]*0.125f : NEG_INF;
                    acc[i][j][1] = k01 ? acc[i][j][1]*0.125f : NEG_INF;
                    acc[i][j][2] = k10 ? acc[i][j][2]*0.125f : NEG_INF;
                    acc[i][j][3] = k11 ? acc[i][j][3]*0.125f : NEG_INF;
                    *(float2*)&Ab[(size_t)lr0 * CS + col]     = *(float2*)&acc[i][j][0];
                    *(float2*)&Ab[(size_t)(lr0+8) * CS + col] = *(float2*)&acc[i][j][2];
                }
            }
            // tile stats
            const int wnIdx = warp >> 1;
            float rmax[4][2];
            #pragma unroll
            for (int i = 0; i < 4; ++i)
                #pragma unroll
                for (int h = 0; h < 2; ++h) {
                    float m = NEG_INF;
                    #pragma unroll
                    for (int j = 0; j < 4; ++j) {
                        m = fmaxf(m, acc[i][j][2*h]);
                        m = fmaxf(m, acc[i][j][2*h+1]);
                    }
                    m = fmaxf(m, __shfl_xor_sync(0xffffffffu, m, 1));
                    m = fmaxf(m, __shfl_xor_sync(0xffffffffu, m, 2));
                    rmax[i][h] = m;
                }
            if (tg == 0) {
                #pragma unroll
                for (int i = 0; i < 4; ++i)
                    #pragma unroll
                    for (int h = 0; h < 2; ++h)
                        sred[wnIdx*128 + wm1 + i*16 + h*8 + g] = rmax[i][h];
            }
            __syncthreads();
            #pragma unroll
            for (int i = 0; i < 4; ++i)
                #pragma unroll
                for (int h = 0; h < 2; ++h) {
                    int rl = wm1 + i*16 + h*8 + g;
                    rmax[i][h] = fmaxf(fmaxf(sred[rl], sred[128+rl]),
                                       fmaxf(sred[256+rl], sred[384+rl]));
                }
            float rsum[4][2];
            #pragma unroll
            for (int i = 0; i < 4; ++i)
                #pragma unroll
                for (int h = 0; h < 2; ++h) {
                    float m = rmax[i][h];
                    float s = 0.f;
                    #pragma unroll
                    for (int j = 0; j < 4; ++j) {
                        float v0 = acc[i][j][2*h], v1 = acc[i][j][2*h+1];
                        s += (v0 == NEG_INF) ? 0.f : __expf(v0 - m);
                        s += (v1 == NEG_INF) ? 0.f : __expf(v1 - m);
                    }
                    s += __shfl_xor_sync(0xffffffffu, s, 1);
                    s += __shfl_xor_sync(0xffffffffu, s, 2);
                    rsum[i][h] = s;
                }
            if (tg == 0) {
                #pragma unroll
                for (int i = 0; i < 4; ++i)
                    #pragma unroll
                    for (int h = 0; h < 2; ++h)
                        ssum[wnIdx*128 + wm1 + i*16 + h*8 + g] = rsum[i][h];
            }
            __syncthreads();
            if (wnIdx == 0 && tg == 0) {
                #pragma unroll
                for (int i = 0; i < 4; ++i)
                    #pragma unroll
                    for (int h = 0; h < 2; ++h) {
                        int rl = wm1 + i*16 + h*8 + g;
                        float tm = rmax[i][h];
                        float ts = ssum[rl] + ssum[128+rl] + ssum[256+rl] + ssum[384+rl];
                        float M = sM[rl], S = sS[rl];
                        float nm = fmaxf(M, tm);
                        float ns;
                        if (nm == NEG_INF) ns = 0.f;
                        else ns = S * __expf(M - nm) + ts * __expf(tm - nm);
                        sM[rl] = nm;
                        sS[rl] = ns;
                    }
            }
            // reset accumulators for next k-tile
            #pragma unroll
            for (int i = 0; i < 4; ++i)
                #pragma unroll
                for (int j = 0; j < 4; ++j)
                    #pragma unroll
                    for (int v = 0; v < 4; ++v)
                        acc[i][j][v] = 0.f;
        }
        if (++stage >= 3) stage = 0;
    }

    // ---- finalize stats, switch smem to pass2 layout ----
    CP_WAIT(0);
    __syncthreads();
    if (tid < 128) sS[tid] = 1.0f / sS[tid];
    __syncthreads();

    // ---- pass 2: R13 pv body ----
    const int wm2 = (warp & 3) * 32, wn2 = (warp >> 2) * 32;
    const int arow = tid >> 2, aq = (tid & 3) * 4;
    const int vrow = tid >> 4, vq = (tid & 15) * 4;

    const float rm0 = sM[arow],      ri0 = sS[arow];
    const float rm1 = sM[64 + arow], ri1 = sS[64 + arow];
    float rmf[2][2], rif[2][2];
    #pragma unroll
    for (int i = 0; i < 2; ++i)
        #pragma unroll
        for (int h = 0; h < 2; ++h) {
            int r = wm2 + i*16 + g + h*8;
            rmf[i][h] = sM[r];
            rif[i][h] = sS[r];
        }
    (void)rmf; (void)rif;

    auto loadPV = [&](int st, int k0) {
        cpa16(&sP[st][arow][aq],      Ab + (size_t)arow * CS + k0 + aq);
        cpa16(&sP[st][64 + arow][aq], Ab + (size_t)(64 + arow) * CS + k0 + aq);
        cpa16(&sV[st][vrow][vq],      Vb + (size_t)(k0 + vrow) * CHD + vq);
        CP_COMMIT();
    };

    loadPV(0, 0);
    loadPV(1, 16);
    loadPV(2, 32);

    float pacc[2][4][4] = {};
    int stage2 = 0;
    for (int c = 0; c < 128; ++c) {
        CP_WAIT(2);
        __syncthreads();
        int pf = c + 3;
        if (pf < 128) loadPV((stage2 + 3) & 3, pf * 16);
        else CP_COMMIT();

        {
            const int k0 = c * 16;
            float4 v0 = *(float4*)&sP[stage2][arow][aq];
            float4 v1 = *(float4*)&sP[stage2][64 + arow][aq];
            v0.x = __expf(v0.x - rm0) * ri0;
            v0.y = __expf(v0.y - rm0) * ri0;
            v0.z = __expf(v0.z - rm0) * ri0;
            v0.w = __expf(v0.w - rm0) * ri0;
            v1.x = __expf(v1.x - rm1) * ri1;
            v1.y = __expf(v1.y - rm1) * ri1;
            v1.z = __expf(v1.z - rm1) * ri1;
            v1.w = __expf(v1.w - rm1) * ri1;
            *(float4*)&Ab[(size_t)arow * CS + k0 + aq]        = v0;
            *(float4*)&Ab[(size_t)(64 + arow) * CS + k0 + aq] = v1;
            float4 r0 = { f2tff(v0.x), f2tff(v0.y), f2tff(v0.z), f2tff(v0.w) };
            float4 r1 = { f2tff(v1.x), f2tff(v1.y), f2tff(v1.z), f2tff(v1.w) };
            *(float4*)&sPr[stage2][arow][aq]      = r0;
            *(float4*)&sPr[stage2][64 + arow][aq] = r1;
        }
        __syncthreads();

        #pragma unroll
        for (int ks = 0; ks < 2; ++ks) {
            const int kk = ks*8 + tg;
            uint32_t au[2][4], bu[4][2];
            #pragma unroll
            for (int i = 0; i < 2; ++i) {
                int m = wm2 + i*16 + g;
                au[i][0] = __float_as_uint(sPr[stage2][m][kk]);
                au[i][1] = __float_as_uint(sPr[stage2][m+8][kk]);
                au[i][2] = __float_as_uint(sPr[stage2][m][kk+4]);
                au[i][3] = __float_as_uint(sPr[stage2][m+8][kk+4]);
            }
            #pragma unroll
            for (int j = 0; j < 4; ++j) {
                int n = wn2 + j*8 + g;
                bu[j][0] = __float_as_uint(sV[stage2][kk][n]);
                bu[j][1] = __float_as_uint(sV[stage2][kk+4][n]);
            }
            #pragma unroll
            for (int i = 0; i < 2; ++i)
                #pragma unroll
                for (int j = 0; j < 4; ++j)
                    mma8(pacc[i][j], au[i], bu[j]);
        }
        stage2 = (stage2 + 1) & 3;
    }

    float* ctxb = g_ctx + ((size_t)bh * CS + q0) * CHD;
    #pragma unroll
    for (int i = 0; i < 2; ++i) {
        int r0 = wm2 + i*16 + g;
        int r1 = r0 + 8;
        #pragma unroll
        for (int j = 0; j < 4; ++j) {
            int col = wn2 + j*8 + 2*tg;
            float2 o0 = { f2tff(pacc[i][j][0]), f2tff(pacc[i][j][1]) };
            float2 o1 = { f2tff(pacc[i][j][2]), f2tff(pacc[i][j][3]) };
            *(float2*)&ctxb[(size_t)r0 * CHD + col] = o0;
            *(float2*)&ctxb[(size_t)r1 * CHD + col] = o1;
        }
    }
}

// ===========================================================================
// outproj (R13): 4-stage BK=16, ctx gather + Wo consumer cvt.
// ===========================================================================
__global__ void __launch_bounds__(256,2) outproj_mma(
    const float* __restrict__ W, const float* __restrict__ bias, float* __restrict__ out)
{
    extern __shared__ float smem[];
    float (*sA)[128][20] = (float(*)[128][20])smem;
    float (*sB)[16][132] = (float(*)[16][132])(smem + 4*128*20);
    const int tid = threadIdx.x, warp = tid >> 5, lane = tid & 31;
    const int g = lane >> 2, tg = lane & 3;
    const int m0 = blockIdx.y * 128, n0 = blockIdx.x * 128;
    const int wm = (warp & 1) * 64, wn = (warp >> 1) * 32;

    const int arow = tid >> 2, aq = (tid & 3) * 4;
    const int brow = tid >> 5, bq = (tid & 31) * 4;

    const int mA0 = m0 + arow,      bA0 = mA0 >> 11, sA0 = mA0 & (CS-1);
    const int mA1 = m0 + 64 + arow, bA1 = mA1 >> 11, sA1 = mA1 & (CS-1);
    const float* ctx0 = g_ctx + ((size_t)bA0*CH*CS + sA0) * CHD;
    const float* ctx1 = g_ctx + ((size_t)bA1*CH*CS + sA1) * CHD;

    auto loadAB = [&](int st, int k0) {
        int k = k0 + aq;
        int h = k >> 6, hd = k & 63;
        cpa16(&sA[st][arow][aq],      ctx0 + (size_t)h * CS * CHD + hd);
        cpa16(&sA[st][64 + arow][aq], ctx1 + (size_t)h * CS * CHD + hd);
        cpa16(&sB[st][brow][bq],      W + (size_t)(k0 + brow) * CD + n0 + bq);
        cpa16(&sB[st][8 + brow][bq],  W + (size_t)(k0 + 8 + brow) * CD + n0 + bq);
        CP_COMMIT();
    };

    loadAB(0, 0);
    loadAB(1, 16);
    loadAB(2, 32);

    float acc[4][4][4] = {};
    int stage = 0;
    for (int c = 0; c < 64; ++c) {
        CP_WAIT(2);
        __syncthreads();
        int pf = c + 3;
        if (pf < 64) loadAB((stage + 3) & 3, pf * 16);
        else CP_COMMIT();
        #pragma unroll
        for (int ks = 0; ks < 2; ++ks) {
            const int kk = ks*8 + tg;
            uint32_t au[4][4], bu[4][2];
            #pragma unroll
            for (int i = 0; i < 4; ++i) {
                int m = wm + i*16 + g;
                au[i][0] = __float_as_uint(sA[stage][m][kk]);
                au[i][1] = __float_as_uint(sA[stage][m+8][kk]);
                au[i][2] = __float_as_uint(sA[stage][m][kk+4]);
                au[i][3] = __float_as_uint(sA[stage][m+8][kk+4]);
            }
            #pragma unroll
            for (int j = 0; j < 4; ++j) {
                int n = wn + j*8 + g;
                bu[j][0] = f2tf(sB[stage][kk][n]);
                bu[j][1] = f2tf(sB[stage][kk+4][n]);
            }
            #pragma unroll
            for (int i = 0; i < 4; ++i)
                #pragma unroll
                for (int j = 0; j < 4; ++j)
                    mma8(acc[i][j], au[i], bu[j]);
        }
        stage = (stage + 1) & 3;
    }

    #pragma unroll
    for (int i = 0; i < 4; ++i) {
        int r0 = m0 + wm + i*16 + g;
        int r1 = r0 + 8;
        #pragma unroll
        for (int j = 0; j < 4; ++j) {
            int col = n0 + wn + j*8 + 2*tg;
            float2 bb = *(const float2*)(bias + col);
            float2 o0 = { acc[i][j][0] + bb.x, acc[i][j][1] + bb.y };
            float2 o1 = { acc[i][j][2] + bb.x, acc[i][j][3] + bb.y };
            *(float2*)&out[(size_t)r0 * CD + col] = o0;
            *(float2*)&out[(size_t)r1 * CD + col] = o1;
        }
    }
}

// ===========================================================================
extern "C" void kernel_launch(void* const* d_in, const int* in_sizes, int n_in,
                              void* d_out, int out_size) {
    const float* query = (const float*)d_in[0];
    const float* key_  = (const float*)d_in[1];
    const float* value = (const float*)d_in[2];
    const float* Wq = (const float*)d_in[3];
    const float* bq = (const float*)d_in[4];
    const float* Wk = (const float*)d_in[5];
    const float* bk = (const float*)d_in[6];
    const float* Wv = (const float*)d_in[7];
    const float* bv = (const float*)d_in[8];
    const float* Wo = (const float*)d_in[9];
    const float* bo = (const float*)d_in[10];
    const void*  mask = d_in[11];

    float* out = (float*)d_out;
    float *qp, *kp, *vp, *attn;
    cudaGetSymbolAddress((void**)&qp, g_q);
    cudaGetSymbolAddress((void**)&kp, g_k);
    cudaGetSymbolAddress((void**)&vp, g_v);
    if ((size_t)out_size >= (size_t)OUT_ELEMS + ATTN_ELEMS) {
        attn = out + OUT_ELEMS;
    } else {
        cudaGetSymbolAddress((void**)&attn, g_attn_fb);
    }

    cudaFuncSetAttribute(proj_mma,    cudaFuncAttributeMaxDynamicSharedMemorySize, PROJ_SMEM);
    cudaFuncSetAttribute(attn_fused,  cudaFuncAttributeMaxDynamicSharedMemorySize, FUSED_SMEM);
    cudaFuncSetAttribute(outproj_mma, cudaFuncAttributeMaxDynamicSharedMemorySize, PROJ_SMEM);

    detect_mask_kernel<<<1, 1>>>((const uint32_t*)mask);

    dim3 pg(CD/128, CM/128);
    proj_mma<<<pg, 256, PROJ_SMEM>>>(query, Wq, bq, qp);
    proj_mma<<<pg, 256, PROJ_SMEM>>>(key_,  Wk, bk, kp);
    proj_mma<<<pg, 256, PROJ_SMEM>>>(value, Wv, bv, vp);

    attn_fused<<<dim3(CS/128, CBH), 256, FUSED_SMEM>>>(mask, attn);
    outproj_mma<<<dim3(CD/128, CM/128), 256, PROJ_SMEM>>>(Wo, bo, out);
}

// round 16
// speedup vs baseline: 1.1055x; 1.0674x over previous
#include <cuda_runtime.h>
#include <cstdint>

#define CB 2
#define CS 2048
#define CD 1024
#define CH 16
#define CHD 64
#define CBH (CB*CH)
#define CM (CB*CS)
#define OUT_ELEMS (CB*CS*CD)
#define ATTN_ELEMS ((size_t)CBH*CS*CS)
#define NKT (CS/128)

__device__ float g_q[CBH*CS*CHD];
__device__ float g_k[CBH*CS*CHD];
__device__ float g_v[CBH*CS*CHD];
__device__ float g_ctx[CBH*CS*CHD];
__device__ float g_attn_fb[(size_t)CBH*CS*CS];
__device__ float g_stat_max[(size_t)CBH*CS*NKT];
__device__ float g_stat_sum[(size_t)CBH*CS*NKT];
__device__ float g_row_m[CBH*CS];
__device__ float g_row_inv[CBH*CS];
__device__ int   g_mask_mode;

#define NEG_INF __int_as_float(0xff800000)

#define PROJ_SMEM (4*(128*20 + 16*132)*4)              // 74752
#define QK_SMEM   (3*2*128*20*4)                       // 61440
#define PV_SMEM   ((4*(128*20 + 16*72) + 4*128*20)*4)  // 100352

__global__ void detect_mask_kernel(const uint32_t* __restrict__ mask) {
    uint32_t w = mask[0];
    int mode = 0;
    if (w == 0x01010101u)      mode = 0;
    else if (w == 1u)          mode = 1;
    else if (w == 0x3F800000u) mode = 2;
    g_mask_mode = mode;
}

__device__ __forceinline__ uint32_t f2tf(float f) {
    uint32_t r;
    asm("cvt.rna.tf32.f32 %0, %1;" : "=r"(r) : "f"(f));
    return r;
}
__device__ __forceinline__ float f2tff(float f) { return __uint_as_float(f2tf(f)); }

__device__ __forceinline__ void mma8(float* c, const uint32_t* a, const uint32_t* b) {
    asm volatile(
        "mma.sync.aligned.m16n8k8.row.col.f32.tf32.tf32.f32 "
        "{%0,%1,%2,%3}, {%4,%5,%6,%7}, {%8,%9}, {%0,%1,%2,%3};"
        : "+f"(c[0]), "+f"(c[1]), "+f"(c[2]), "+f"(c[3])
        : "r"(a[0]), "r"(a[1]), "r"(a[2]), "r"(a[3]), "r"(b[0]), "r"(b[1]));
}

__device__ __forceinline__ void cpa16(const void* smem, const void* gmem) {
    uint32_t s = (uint32_t)__cvta_generic_to_shared(smem);
    asm volatile("cp.async.cg.shared.global [%0], [%1], 16;" :: "r"(s), "l"(gmem));
}
#define CP_COMMIT() asm volatile("cp.async.commit_group;")
#define CP_WAIT(n)  asm volatile("cp.async.wait_group %0;" :: "n"(n))

// ===========================================================================
// proj_batched: Q/K/V projections in ONE launch; blockIdx.z picks operand set.
// Body identical to R13 proj (4-stage BK=16, consumer cvt, rounded scatter).
// ===========================================================================
__global__ void __launch_bounds__(256,2) proj_batched(
    const float* __restrict__ A0, const float* __restrict__ A1, const float* __restrict__ A2,
    const float* __restrict__ W0, const float* __restrict__ W1, const float* __restrict__ W2,
    const float* __restrict__ bias0, const float* __restrict__ bias1, const float* __restrict__ bias2,
    float* __restrict__ dst0, float* __restrict__ dst1, float* __restrict__ dst2)
{
    extern __shared__ float smem[];
    float (*sA)[128][20] = (float(*)[128][20])smem;
    float (*sB)[16][132] = (float(*)[16][132])(smem + 4*128*20);
    const int tid = threadIdx.x, warp = tid >> 5, lane = tid & 31;
    const int g = lane >> 2, tg = lane & 3;
    const int m0 = blockIdx.y * 128, n0 = blockIdx.x * 128;
    const int wm = (warp & 1) * 64, wn = (warp >> 1) * 32;
    const int which = blockIdx.z;

    const float* A    = (which == 0) ? A0 : (which == 1) ? A1 : A2;
    const float* W    = (which == 0) ? W0 : (which == 1) ? W1 : W2;
    const float* bias = (which == 0) ? bias0 : (which == 1) ? bias1 : bias2;
    float* dst        = (which == 0) ? dst0 : (which == 1) ? dst1 : dst2;

    const int arow = tid >> 2, aq = (tid & 3) * 4;
    const int brow = tid >> 5, bq = (tid & 31) * 4;

    auto loadAB = [&](int st, int k0) {
        cpa16(&sA[st][arow][aq],      A + (size_t)(m0 + arow) * CD + k0 + aq);
        cpa16(&sA[st][64 + arow][aq], A + (size_t)(m0 + 64 + arow) * CD + k0 + aq);
        cpa16(&sB[st][brow][bq],      W + (size_t)(k0 + brow) * CD + n0 + bq);
        cpa16(&sB[st][8 + brow][bq],  W + (size_t)(k0 + 8 + brow) * CD + n0 + bq);
        CP_COMMIT();
    };

    loadAB(0, 0);
    loadAB(1, 16);
    loadAB(2, 32);

    float acc[4][4][4] = {};
    int stage = 0;
    for (int c = 0; c < 64; ++c) {
        CP_WAIT(2);
        __syncthreads();
        int pf = c + 3;
        if (pf < 64) loadAB((stage + 3) & 3, pf * 16);
        else CP_COMMIT();
        #pragma unroll
        for (int ks = 0; ks < 2; ++ks) {
            const int kk = ks*8 + tg;
            uint32_t au[4][4], bu[4][2];
            #pragma unroll
            for (int i = 0; i < 4; ++i) {
                int m = wm + i*16 + g;
                au[i][0] = f2tf(sA[stage][m][kk]);
                au[i][1] = f2tf(sA[stage][m+8][kk]);
                au[i][2] = f2tf(sA[stage][m][kk+4]);
                au[i][3] = f2tf(sA[stage][m+8][kk+4]);
            }
            #pragma unroll
            for (int j = 0; j < 4; ++j) {
                int n = wn + j*8 + g;
                bu[j][0] = f2tf(sB[stage][kk][n]);
                bu[j][1] = f2tf(sB[stage][kk+4][n]);
            }
            #pragma unroll
            for (int i = 0; i < 4; ++i)
                #pragma unroll
                for (int j = 0; j < 4; ++j)
                    mma8(acc[i][j], au[i], bu[j]);
        }
        stage = (stage + 1) & 3;
    }

    #pragma unroll
    for (int i = 0; i < 4; ++i) {
        int r0 = m0 + wm + i*16 + g;
        int r1 = r0 + 8;
        int b0i = r0 >> 11, s0 = r0 & (CS-1);
        int b1i = r1 >> 11, s1 = r1 & (CS-1);
        #pragma unroll
        for (int j = 0; j < 4; ++j) {
            int col = n0 + wn + j*8 + 2*tg;
            int h = col >> 6, hd = col & 63;
            float2 bb = *(const float2*)(bias + col);
            float2 o0 = { f2tff(acc[i][j][0] + bb.x), f2tff(acc[i][j][1] + bb.y) };
            float2 o1 = { f2tff(acc[i][j][2] + bb.x), f2tff(acc[i][j][3] + bb.y) };
            *(float2*)&dst[((size_t)(b0i*CH + h)*CS + s0)*CHD + hd] = o0;
            *(float2*)&dst[((size_t)(b1i*CH + h)*CS + s1)*CHD + hd] = o1;
        }
    }
}

// ===========================================================================
// qk (R13): raw scores + per-(row, tile) softmax stats.
// ===========================================================================
__global__ void __launch_bounds__(256,2) qk_mma(
    const void* __restrict__ maskp, float* __restrict__ scores)
{
    extern __shared__ float smem[];
    float (*sQ)[128][20] = (float(*)[128][20])smem;
    float (*sK)[128][20] = (float(*)[128][20])(smem + 3*128*20);
    const int tid = threadIdx.x, warp = tid >> 5, lane = tid & 31;
    const int g = lane >> 2, tg = lane & 3;
    const int bh = blockIdx.z;
    const int q0 = blockIdx.y * 128, k0t = blockIdx.x * 128;
    const int wm = (warp & 1) * 64, wn = (warp >> 1) * 32;
    const float* Qb = g_q + (size_t)bh * CS * CHD;
    const float* Kb = g_k + (size_t)bh * CS * CHD;

    const int arow = tid >> 2, aq = (tid & 3) * 4;

    auto loadQK = [&](int st, int d0) {
        cpa16(&sQ[st][arow][aq],      Qb + (size_t)(q0 + arow) * CHD + d0 + aq);
        cpa16(&sQ[st][64 + arow][aq], Qb + (size_t)(q0 + 64 + arow) * CHD + d0 + aq);
        cpa16(&sK[st][arow][aq],      Kb + (size_t)(k0t + arow) * CHD + d0 + aq);
        cpa16(&sK[st][64 + arow][aq], Kb + (size_t)(k0t + 64 + arow) * CHD + d0 + aq);
        CP_COMMIT();
    };

    loadQK(0, 0);
    loadQK(1, 16);

    float acc[4][4][4] = {};
    int stage = 0;
    for (int c = 0; c < 4; ++c) {
        CP_WAIT(1);
        __syncthreads();
        int pf = c + 2;
        if (pf < 4) {
            int st = stage + 2; if (st >= 3) st -= 3;
            loadQK(st, pf * 16);
        } else CP_COMMIT();
        #pragma unroll
        for (int ks = 0; ks < 2; ++ks) {
            const int kk = ks*8 + tg;
            uint32_t au[4][4], bu[4][2];
            #pragma unroll
            for (int i = 0; i < 4; ++i) {
                int m = wm + i*16 + g;
                au[i][0] = __float_as_uint(sQ[stage][m][kk]);
                au[i][1] = __float_as_uint(sQ[stage][m+8][kk]);
                au[i][2] = __float_as_uint(sQ[stage][m][kk+4]);
                au[i][3] = __float_as_uint(sQ[stage][m+8][kk+4]);
            }
            #pragma unroll
            for (int j = 0; j < 4; ++j) {
                int n = wn + j*8 + g;
                bu[j][0] = __float_as_uint(sK[stage][n][kk]);
                bu[j][1] = __float_as_uint(sK[stage][n][kk+4]);
            }
            #pragma unroll
            for (int i = 0; i < 4; ++i)
                #pragma unroll
                for (int j = 0; j < 4; ++j)
                    mma8(acc[i][j], au[i], bu[j]);
        }
        if (++stage >= 3) stage = 0;
    }

    const int mode = g_mask_mode;
    float* srow = scores + (size_t)bh * CS * CS;
    #pragma unroll
    for (int i = 0; i < 4; ++i) {
        int r0 = q0 + wm + i*16 + g;
        int r1 = r0 + 8;
        #pragma unroll
        for (int j = 0; j < 4; ++j) {
            int col = k0t + wn + j*8 + 2*tg;
            size_t off0 = (size_t)r0 * CS + col;
            size_t off1 = (size_t)r1 * CS + col;
            bool k00, k01, k10, k11;
            if (mode == 0) {
                uchar2 a = *(const uchar2*)((const unsigned char*)maskp + off0);
                uchar2 b = *(const uchar2*)((const unsigned char*)maskp + off1);
                k00 = a.x; k01 = a.y; k10 = b.x; k11 = b.y;
            } else if (mode == 1) {
                int2 a = *(const int2*)((const int*)maskp + off0);
                int2 b = *(const int2*)((const int*)maskp + off1);
                k00 = a.x; k01 = a.y; k10 = b.x; k11 = b.y;
            } else {
                float2 a = *(const float2*)((const float*)maskp + off0);
                float2 b = *(const float2*)((const float*)maskp + off1);
                k00 = a.x != 0.f; k01 = a.y != 0.f; k10 = b.x != 0.f; k11 = b.y != 0.f;
            }
            acc[i][j][0] = k00 ? acc[i][j][0]*0.125f : NEG_INF;
            acc[i][j][1] = k01 ? acc[i][j][1]*0.125f : NEG_INF;
            acc[i][j][2] = k10 ? acc[i][j][2]*0.125f : NEG_INF;
            acc[i][j][3] = k11 ? acc[i][j][3]*0.125f : NEG_INF;
            *(float2*)(srow + off0) = *(float2*)&acc[i][j][0];
            *(float2*)(srow + off1) = *(float2*)&acc[i][j][2];
        }
    }

    float* sred = smem;
    float* ssum = smem + 512;
    const int wnIdx = warp >> 1;
    __syncthreads();

    float rmax[4][2];
    #pragma unroll
    for (int i = 0; i < 4; ++i)
        #pragma unroll
        for (int h = 0; h < 2; ++h) {
            float m = NEG_INF;
            #pragma unroll
            for (int j = 0; j < 4; ++j) {
                m = fmaxf(m, acc[i][j][2*h]);
                m = fmaxf(m, acc[i][j][2*h+1]);
            }
            m = fmaxf(m, __shfl_xor_sync(0xffffffffu, m, 1));
            m = fmaxf(m, __shfl_xor_sync(0xffffffffu, m, 2));
            rmax[i][h] = m;
        }
    if (tg == 0) {
        #pragma unroll
        for (int i = 0; i < 4; ++i)
            #pragma unroll
            for (int h = 0; h < 2; ++h)
                sred[wnIdx*128 + wm + i*16 + h*8 + g] = rmax[i][h];
    }
    __syncthreads();
    #pragma unroll
    for (int i = 0; i < 4; ++i)
        #pragma unroll
        for (int h = 0; h < 2; ++h) {
            int rl = wm + i*16 + h*8 + g;
            rmax[i][h] = fmaxf(fmaxf(sred[rl], sred[128+rl]),
                               fmaxf(sred[256+rl], sred[384+rl]));
        }
    float rsum[4][2];
    #pragma unroll
    for (int i = 0; i < 4; ++i)
        #pragma unroll
        for (int h = 0; h < 2; ++h) {
            float m = rmax[i][h];
            float s = 0.f;
            #pragma unroll
            for (int j = 0; j < 4; ++j) {
                float v0 = acc[i][j][2*h], v1 = acc[i][j][2*h+1];
                s += (v0 == NEG_INF) ? 0.f : __expf(v0 - m);
                s += (v1 == NEG_INF) ? 0.f : __expf(v1 - m);
            }
            s += __shfl_xor_sync(0xffffffffu, s, 1);
            s += __shfl_xor_sync(0xffffffffu, s, 2);
            rsum[i][h] = s;
        }
    if (tg == 0) {
        #pragma unroll
        for (int i = 0; i < 4; ++i)
            #pragma unroll
            for (int h = 0; h < 2; ++h)
                ssum[wnIdx*128 + wm + i*16 + h*8 + g] = rsum[i][h];
    }
    __syncthreads();
    if (wnIdx == 0 && tg == 0) {
        #pragma unroll
        for (int i = 0; i < 4; ++i)
            #pragma unroll
            for (int h = 0; h < 2; ++h) {
                int rl = wm + i*16 + h*8 + g;
                float s = ssum[rl] + ssum[128+rl] + ssum[256+rl] + ssum[384+rl];
                size_t sidx = ((size_t)bh*CS + q0 + rl)*NKT + blockIdx.x;
                g_stat_max[sidx] = rmax[i][h];
                g_stat_sum[sidx] = s;
            }
    }
}

// ===========================================================================
__global__ void __launch_bounds__(256) stat_reduce()
{
    int idx = blockIdx.x * 256 + threadIdx.x;
    const float* pm = g_stat_max + (size_t)idx * NKT;
    const float* ps = g_stat_sum + (size_t)idx * NKT;
    float M = NEG_INF;
    #pragma unroll
    for (int t = 0; t < NKT; ++t) M = fmaxf(M, pm[t]);
    float S = 0.f;
    #pragma unroll
    for (int t = 0; t < NKT; ++t) S += ps[t] * __expf(pm[t] - M);
    g_row_m[idx] = M;
    g_row_inv[idx] = 1.0f / S;
}

// ===========================================================================
// pv (R13): exp-once writer phase + pure-LDS consumers.
// ===========================================================================
__global__ void __launch_bounds__(256,2) pv_mma(float* __restrict__ attn)
{
    extern __shared__ float smem[];
    float (*sP)[128][20]  = (float(*)[128][20])smem;
    float (*sV)[16][72]   = (float(*)[16][72])(smem + 4*128*20);
    float (*sPr)[128][20] = (float(*)[128][20])(smem + 4*128*20 + 4*16*72);
    const int tid = threadIdx.x, warp = tid >> 5, lane = tid & 31;
    const int g = lane >> 2, tg = lane & 3;
    const int bh = blockIdx.y, m0 = blockIdx.x * 128;
    const int wm = (warp & 3) * 32, wn = (warp >> 2) * 32;
    float* Ab = attn + (size_t)bh * CS * CS;
    const float* Vb = g_v + (size_t)bh * CS * CHD;

    const int arow = tid >> 2, aq = (tid & 3) * 4;
    const int vrow = tid >> 4, vq = (tid & 15) * 4;

    const float rm0 = g_row_m[bh*CS + m0 + arow];
    const float ri0 = g_row_inv[bh*CS + m0 + arow];
    const float rm1 = g_row_m[bh*CS + m0 + 64 + arow];
    const float ri1 = g_row_inv[bh*CS + m0 + 64 + arow];

    auto loadPV = [&](int st, int k0) {
        cpa16(&sP[st][arow][aq],      Ab + (size_t)(m0 + arow) * CS + k0 + aq);
        cpa16(&sP[st][64 + arow][aq], Ab + (size_t)(m0 + 64 + arow) * CS + k0 + aq);
        cpa16(&sV[st][vrow][vq],      Vb + (size_t)(k0 + vrow) * CHD + vq);
        CP_COMMIT();
    };

    loadPV(0, 0);
    loadPV(1, 16);
    loadPV(2, 32);

    float acc[2][4][4] = {};
    int stage = 0;
    for (int c = 0; c < 128; ++c) {
        CP_WAIT(2);
        __syncthreads();
        int pf = c + 3;
        if (pf < 128) loadPV((stage + 3) & 3, pf * 16);
        else CP_COMMIT();

        {
            const int k0 = c * 16;
            float4 v0 = *(float4*)&sP[stage][arow][aq];
            float4 v1 = *(float4*)&sP[stage][64 + arow][aq];
            v0.x = __expf(v0.x - rm0) * ri0;
            v0.y = __expf(v0.y - rm0) * ri0;
            v0.z = __expf(v0.z - rm0) * ri0;
            v0.w = __expf(v0.w - rm0) * ri0;
            v1.x = __expf(v1.x - rm1) * ri1;
            v1.y = __expf(v1.y - rm1) * ri1;
            v1.z = __expf(v1.z - rm1) * ri1;
            v1.w = __expf(v1.w - rm1) * ri1;
            *(float4*)&Ab[(size_t)(m0 + arow) * CS + k0 + aq]      = v0;
            *(float4*)&Ab[(size_t)(m0 + 64 + arow) * CS + k0 + aq] = v1;
            float4 r0 = { f2tff(v0.x), f2tff(v0.y), f2tff(v0.z), f2tff(v0.w) };
            float4 r1 = { f2tff(v1.x), f2tff(v1.y), f2tff(v1.z), f2tff(v1.w) };
            *(float4*)&sPr[stage][arow][aq]      = r0;
            *(float4*)&sPr[stage][64 + arow][aq] = r1;
        }
        __syncthreads();

        #pragma unroll
        for (int ks = 0; ks < 2; ++ks) {
            const int kk = ks*8 + tg;
            uint32_t au[2][4], bu[4][2];
            #pragma unroll
            for (int i = 0; i < 2; ++i) {
                int m = wm + i*16 + g;
                au[i][0] = __float_as_uint(sPr[stage][m][kk]);
                au[i][1] = __float_as_uint(sPr[stage][m+8][kk]);
                au[i][2] = __float_as_uint(sPr[stage][m][kk+4]);
                au[i][3] = __float_as_uint(sPr[stage][m+8][kk+4]);
            }
            #pragma unroll
            for (int j = 0; j < 4; ++j) {
                int n = wn + j*8 + g;
                bu[j][0] = __float_as_uint(sV[stage][kk][n]);
                bu[j][1] = __float_as_uint(sV[stage][kk+4][n]);
            }
            #pragma unroll
            for (int i = 0; i < 2; ++i)
                #pragma unroll
                for (int j = 0; j < 4; ++j)
                    mma8(acc[i][j], au[i], bu[j]);
        }
        stage = (stage + 1) & 3;
    }

    float* ctxb = g_ctx + (size_t)bh * CS * CHD;
    #pragma unroll
    for (int i = 0; i < 2; ++i) {
        int r0 = m0 + wm + i*16 + g;
        int r1 = r0 + 8;
        #pragma unroll
        for (int j = 0; j < 4; ++j) {
            int col = wn + j*8 + 2*tg;
            float2 o0 = { f2tff(acc[i][j][0]), f2tff(acc[i][j][1]) };
            float2 o1 = { f2tff(acc[i][j][2]), f2tff(acc[i][j][3]) };
            *(float2*)&ctxb[(size_t)r0 * CHD + col] = o0;
            *(float2*)&ctxb[(size_t)r1 * CHD + col] = o1;
        }
    }
}

// ===========================================================================
// outproj (R13): 4-stage BK=16, ctx gather + Wo consumer cvt.
// ===========================================================================
__global__ void __launch_bounds__(256,2) outproj_mma(
    const float* __restrict__ W, const float* __restrict__ bias, float* __restrict__ out)
{
    extern __shared__ float smem[];
    float (*sA)[128][20] = (float(*)[128][20])smem;
    float (*sB)[16][132] = (float(*)[16][132])(smem + 4*128*20);
    const int tid = threadIdx.x, warp = tid >> 5, lane = tid & 31;
    const int g = lane >> 2, tg = lane & 3;
    const int m0 = blockIdx.y * 128, n0 = blockIdx.x * 128;
    const int wm = (warp & 1) * 64, wn = (warp >> 1) * 32;

    const int arow = tid >> 2, aq = (tid & 3) * 4;
    const int brow = tid >> 5, bq = (tid & 31) * 4;

    const int mA0 = m0 + arow,      bA0 = mA0 >> 11, sA0 = mA0 & (CS-1);
    const int mA1 = m0 + 64 + arow, bA1 = mA1 >> 11, sA1 = mA1 & (CS-1);
    const float* ctx0 = g_ctx + ((size_t)bA0*CH*CS + sA0) * CHD;
    const float* ctx1 = g_ctx + ((size_t)bA1*CH*CS + sA1) * CHD;

    auto loadAB = [&](int st, int k0) {
        int k = k0 + aq;
        int h = k >> 6, hd = k & 63;
        cpa16(&sA[st][arow][aq],      ctx0 + (size_t)h * CS * CHD + hd);
        cpa16(&sA[st][64 + arow][aq], ctx1 + (size_t)h * CS * CHD + hd);
        cpa16(&sB[st][brow][bq],      W + (size_t)(k0 + brow) * CD + n0 + bq);
        cpa16(&sB[st][8 + brow][bq],  W + (size_t)(k0 + 8 + brow) * CD + n0 + bq);
        CP_COMMIT();
    };

    loadAB(0, 0);
    loadAB(1, 16);
    loadAB(2, 32);

    float acc[4][4][4] = {};
    int stage = 0;
    for (int c = 0; c < 64; ++c) {
        CP_WAIT(2);
        __syncthreads();
        int pf = c + 3;
        if (pf < 64) loadAB((stage + 3) & 3, pf * 16);
        else CP_COMMIT();
        #pragma unroll
        for (int ks = 0; ks < 2; ++ks) {
            const int kk = ks*8 + tg;
            uint32_t au[4][4], bu[4][2];
            #pragma unroll
            for (int i = 0; i < 4; ++i) {
                int m = wm + i*16 + g;
                au[i][0] = __float_as_uint(sA[stage][m][kk]);
                au[i][1] = __float_as_uint(sA[stage][m+8][kk]);
                au[i][2] = __float_as_uint(sA[stage][m][kk+4]);
                au[i][3] = __float_as_uint(sA[stage][m+8][kk+4]);
            }
            #pragma unroll
            for (int j = 0; j < 4; ++j) {
                int n = wn + j*8 + g;
                bu[j][0] = f2tf(sB[stage][kk][n]);
                bu[j][1] = f2tf(sB[stage][kk+4][n]);
            }
            #pragma unroll
            for (int i = 0; i < 4; ++i)
                #pragma unroll
                for (int j = 0; j < 4; ++j)
                    mma8(acc[i][j], au[i], bu[j]);
        }
        stage = (stage + 1) & 3;
    }

    #pragma unroll
    for (int i = 0; i < 4; ++i) {
        int r0 = m0 + wm + i*16 + g;
        int r1 = r0 + 8;
        #pragma unroll
        for (int j = 0; j < 4; ++j) {
            int col = n0 + wn + j*8 + 2*tg;
            float2 bb = *(const float2*)(bias + col);
            float2 o0 = { acc[i][j][0] + bb.x, acc[i][j][1] + bb.y };
            float2 o1 = { acc[i][j][2] + bb.x, acc[i][j][3] + bb.y };
            *(float2*)&out[(size_t)r0 * CD + col] = o0;
            *(float2*)&out[(size_t)r1 * CD + col] = o1;
        }
    }
}

// ===========================================================================
extern "C" void kernel_launch(void* const* d_in, const int* in_sizes, int n_in,
                              void* d_out, int out_size) {
    const float* query = (const float*)d_in[0];
    const float* key_  = (const float*)d_in[1];
    const float* value = (const float*)d_in[2];
    const float* Wq = (const float*)d_in[3];
    const float* bq = (const float*)d_in[4];
    const float* Wk = (const float*)d_in[5];
    const float* bk = (const float*)d_in[6];
    const float* Wv = (const float*)d_in[7];
    const float* bv = (const float*)d_in[8];
    const float* Wo = (const float*)d_in[9];
    const float* bo = (const float*)d_in[10];
    const void*  mask = d_in[11];

    float* out = (float*)d_out;
    float *qp, *kp, *vp, *attn;
    cudaGetSymbolAddress((void**)&qp, g_q);
    cudaGetSymbolAddress((void**)&kp, g_k);
    cudaGetSymbolAddress((void**)&vp, g_v);
    if ((size_t)out_size >= (size_t)OUT_ELEMS + ATTN_ELEMS) {
        attn = out + OUT_ELEMS;
    } else {
        cudaGetSymbolAddress((void**)&attn, g_attn_fb);
    }

    cudaFuncSetAttribute(proj_batched, cudaFuncAttributeMaxDynamicSharedMemorySize, PROJ_SMEM);
    cudaFuncSetAttribute(qk_mma,       cudaFuncAttributeMaxDynamicSharedMemorySize, QK_SMEM);
    cudaFuncSetAttribute(pv_mma,       cudaFuncAttributeMaxDynamicSharedMemorySize, PV_SMEM);
    cudaFuncSetAttribute(outproj_mma,  cudaFuncAttributeMaxDynamicSharedMemorySize, PROJ_SMEM);

    detect_mask_kernel<<<1, 1>>>((const uint32_t*)mask);

    proj_batched<<<dim3(CD/128, CM/128, 3), 256, PROJ_SMEM>>>(
        query, key_, value, Wq, Wk, Wv, bq, bk, bv, qp, kp, vp);

    qk_mma<<<dim3(CS/128, CS/128, CBH), 256, QK_SMEM>>>(mask, attn);
    stat_reduce<<<CBH*CS/256, 256>>>();
    pv_mma<<<dim3(CS/128, CBH), 256, PV_SMEM>>>(attn);
    outproj_mma<<<dim3(CD/128, CM/128), 256, PROJ_SMEM>>>(Wo, bo, out);
}